// round 14
// baseline (speedup 1.0000x reference)
#include <cuda_runtime.h>
#include <cstdint>

// Problem constants
#define NROWS    22743
#define ROWB     340            // bytes per row (85 f32)
#define NB       64
#define NCELLS   7581           // 76^2 + 38^2 + 19^2
#define BLK      512
#define CPB      170            // cells per block (510 rows, 512 threads)
#define GX       ((NCELLS + CPB - 1) / CPB)  // 45
#define NBLOCKS  (GX * NB)                    // 2880

__device__ float4       g_part4[NBLOCKS];
__device__ unsigned int g_cnt = 0;

__device__ __forceinline__ float bce_sig(float z, float t) {
    return __logf(1.0f + __expf(-z)) + (1.0f - t) * z;
}
__device__ __forceinline__ float bce_raw(float p, float t) {
    float pc = fmaxf(p, 1e-12f);
    return -(t * __logf(pc) + (1.0f - t) * __logf(1.0f - pc));
}

__global__ void __launch_bounds__(BLK)
yolo_fused(const float* __restrict__ x, const float* __restrict__ tgt,
           float* __restrict__ out) {
    const int ltid = threadIdx.x;
    const int b    = blockIdx.y;
    const int cell = blockIdx.x * CPB + ltid / 3;   // this thread's cell
    const int k    = ltid - 3 * (ltid / 3);         // anchor index within cell

    __shared__ float inS[BLK], ueS[BLK];

    float s_n = 0.f, s_A = 0.f, s_C = 0.f, s_O = 0.f;

    const bool active = (ltid < 3 * CPB) && (cell < NCELLS);

    // Per-level / per-anchor constants
    float g = 0.f, objw = 0.f, AWk = 1.f, AHk = 1.f;
    if (active) {
        if (cell < 5776) {               // grid 76
            g = 76.f; objw = 1.0f / (64.f * 17328.f);
            AWk = (k==0)?1.25f  :(k==1)?2.0f   :4.125f;
            AHk = (k==0)?1.625f :(k==1)?3.75f  :2.875f;
        } else if (cell < 7220) {        // grid 38
            g = 38.f; objw = 1.0f / (64.f * 4332.f);
            AWk = (k==0)?1.875f :(k==1)?3.875f :3.6875f;
            AHk = (k==0)?3.8125f:(k==1)?2.8125f:7.4375f;
        } else {                         // grid 19
            g = 19.f; objw = 1.0f / (64.f * 1083.f);
            AWk = (k==0)?3.625f  :(k==1)?4.875f :11.65625f;
            AHk = (k==0)?2.8125f :(k==1)?6.1875f:10.1875f;
        }
    }

    const size_t rb = ((size_t)b * NROWS + (size_t)3 * cell + k) * (size_t)ROWB;
    const char* tb = (const char*)tgt;
    const char* xb = (const char*)x;

    float t2 = 0.f, t3 = 0.f, t4 = 0.f, x4 = 0.f;
    float in_ = 0.f, ue = 1e-12f;
    if (active) {
        // 4 scalar loads; warp lane addresses stride 340B -> dense 10.9KB window
        t2 = __ldcg((const float*)(tb + rb + 8));
        t3 = __ldcg((const float*)(tb + rb + 12));
        t4 = __ldcg((const float*)(tb + rb + 16));
        x4 = __ldcs((const float*)(xb + rb + 16));

        float gw = t2 * g, gh = t3 * g;
        in_ = fminf(gw, AWk) * fminf(gh, AHk);
        ue  = gw * gh + AWk * AHk - in_ + 1e-12f;
    }

    // Exchange inter/ue within the triple via smem
    inS[ltid] = in_;
    ueS[ltid] = ue;
    __syncthreads();

    if (active) {
        int base = 3 * (ltid / 3);
        float in0 = inS[base],     ue0 = ueS[base];
        float in1 = inS[base + 1], ue1 = ueS[base + 1];
        float in2 = inS[base + 2], ue2 = ueS[base + 2];

        // argmax(iou) via cross-multiplication, first-wins ties
        int best = 0;
        float inb = in0, ueb = ue0;
        if (in1 * ue0 > in0 * ue1) { best = 1; inb = in1; ueb = ue1; }
        if (in2 * ueb > inb * ue2) { best = 2; }

        float keep = ((in_ <= 0.7f * ue) || (k == best)) ? 1.f : 0.f;
        float z  = x4 * keep;
        float tt = t4 * keep;
        s_O = (__logf(1.0f + __expf(-z)) + (1.0f - tt) * z) * objw;

        if (t4 > 0.f) {                  // ~2% of rows: masked losses
            const float* trk = (const float*)(tb + rb);
            const float* xrk = (const float*)(xb + rb);
            float t0 = trk[0], t1 = trk[1];
            float x0 = xrk[0], x1 = xrk[1], x2 = xrk[2], x3 = xrk[3];
            s_n = 1.f;
            s_A = bce_sig(x0, t0) + bce_sig(x1, t1)
                + bce_raw(x2, t2) + bce_raw(x3, t3);
            s_C = bce_sig(x4, 1.0f);
        }
    }
    __syncthreads();   // smem reuse barrier (inS/ueS -> sm)

    // ---- Deterministic fixed-order block tree ----
    __shared__ float sm[BLK * 4];
    sm[ltid]           = s_n;
    sm[ltid + BLK]     = s_A;
    sm[ltid + 2 * BLK] = s_C;
    sm[ltid + 3 * BLK] = s_O;
    __syncthreads();
    #pragma unroll
    for (int off = BLK / 2; off > 0; off >>= 1) {
        if (ltid < off) {
            sm[ltid]           += sm[ltid + off];
            sm[ltid + BLK]     += sm[ltid + BLK + off];
            sm[ltid + 2 * BLK] += sm[ltid + 2 * BLK + off];
            sm[ltid + 3 * BLK] += sm[ltid + 3 * BLK + off];
        }
        __syncthreads();
    }

    __shared__ int amLast;
    if (ltid == 0) {
        int bid = blockIdx.y * gridDim.x + blockIdx.x;
        g_part4[bid] = make_float4(sm[0], sm[BLK], sm[2 * BLK], sm[3 * BLK]);
        __threadfence();
        unsigned v = atomicAdd(&g_cnt, 1u);
        amLast = (v == NBLOCKS - 1);
    }
    __syncthreads();

    if (amLast) {
        __threadfence();
        __shared__ double dm[BLK * 4];
        double a0d = 0, a1d = 0, a2d = 0, a3d = 0;
        for (int i = ltid; i < NBLOCKS; i += BLK) {
            float4 p = __ldcg(&g_part4[i]);
            a0d += (double)p.x; a1d += (double)p.y;
            a2d += (double)p.z; a3d += (double)p.w;
        }
        dm[ltid]           = a0d;
        dm[ltid + BLK]     = a1d;
        dm[ltid + 2 * BLK] = a2d;
        dm[ltid + 3 * BLK] = a3d;
        __syncthreads();
        #pragma unroll
        for (int off = BLK / 2; off > 0; off >>= 1) {
            if (ltid < off) {
                dm[ltid]           += dm[ltid + off];
                dm[ltid + BLK]     += dm[ltid + BLK + off];
                dm[ltid + 2 * BLK] += dm[ltid + 2 * BLK + off];
                dm[ltid + 3 * BLK] += dm[ltid + 3 * BLK + off];
            }
            __syncthreads();
        }
        if (ltid == 0) {
            double n = dm[0];
            if (n < 1.0) n = 1.0;
            double r = dm[BLK] / (2.0 * n)
                     + dm[2 * BLK] / n
                     + dm[3 * BLK];
            out[0] = (float)r;
            g_cnt = 0;
        }
    }
}

extern "C" void kernel_launch(void* const* d_in, const int* in_sizes, int n_in,
                              void* d_out, int out_size) {
    const float* x   = (const float*)d_in[0];
    const float* tgt = (const float*)d_in[1];
    dim3 grid(GX, NB);
    yolo_fused<<<grid, BLK>>>(x, tgt, (float*)d_out);
}